// round 2
// baseline (speedup 1.0000x reference)
#include <cuda_runtime.h>
#include <cuda_bf16.h>
#include <math.h>

// ---------------- problem constants ----------------
#define S      2048
#define Hdim   2048
#define NH     16
#define DN     128
#define DR     64
#define DV     128
#define QL     1536
#define KL     512
#define DFULL  (DN + DR)            // 192
#define FUSED_N (QL + KL + DR)      // 2112
#define QB_N   (NH * (DN + DR))     // 3072
#define KVB_N  (NH * (DN + DV))     // 4096

// ---------------- scratch (device globals; no allocation allowed) ----------------
__device__ float g_fused[S * FUSED_N];     // 2048 x 2112
__device__ float g_qn[S * QL];             // rmsnorm(q_c)
__device__ float g_kvn[S * KL];            // rmsnorm(kv_c)
__device__ float g_qp[S * QB_N];           // q projection
__device__ float g_kvp[S * KVB_N];         // kv projection
__device__ float g_Q[NH * S * DFULL];      // [h][s][192], pre-scaled
__device__ float g_K[NH * S * DFULL];      // [h][s][192]
__device__ float g_V[NH * S * DV];         // [h][s][128]
__device__ float g_attn[S * NH * DV];      // [s][h*128+dv]

// ---------------- generic tiled SGEMM: C[M,N] = A[M,K] @ B[K,N] ----------------
// BM=128, BN=64, BK=16, 256 threads (16x16), thread tile 8x4.
// Requires: M%128==0, N%64==0, K%16==0, N%4==0 (all satisfied here).
__global__ __launch_bounds__(256) void sgemm_128x64(
    const float* __restrict__ A, const float* __restrict__ B,
    float* __restrict__ C, int M, int N, int K)
{
    __shared__ float As[16][128];
    __shared__ float Bs[16][64];

    const int tid = threadIdx.x;
    const int tx = tid & 15;       // 0..15 -> 4 cols each
    const int ty = tid >> 4;       // 0..15 -> 8 rows each
    const int row0 = blockIdx.y * 128;
    const int col0 = blockIdx.x * 64;

    float acc[8][4];
#pragma unroll
    for (int i = 0; i < 8; i++)
#pragma unroll
        for (int j = 0; j < 4; j++) acc[i][j] = 0.f;

    for (int k0 = 0; k0 < K; k0 += 16) {
        // load A tile 128x16 (512 float4), store transposed As[k][r]
#pragma unroll
        for (int t = 0; t < 2; t++) {
            int f = tid + t * 256;           // 0..511
            int r = f >> 2;                  // 0..127
            int kc = (f & 3) << 2;           // 0,4,8,12
            float4 va = *(const float4*)&A[(size_t)(row0 + r) * K + k0 + kc];
            As[kc + 0][r] = va.x;
            As[kc + 1][r] = va.y;
            As[kc + 2][r] = va.z;
            As[kc + 3][r] = va.w;
        }
        // load B tile 16x64 (256 float4)
        {
            int r = tid >> 4;                // 0..15
            int c = (tid & 15) << 2;         // 0..60
            *(float4*)&Bs[r][c] = *(const float4*)&B[(size_t)(k0 + r) * N + col0 + c];
        }
        __syncthreads();

#pragma unroll
        for (int kk = 0; kk < 16; kk++) {
            float a[8], b[4];
            *(float4*)&a[0] = *(const float4*)&As[kk][ty * 8];
            *(float4*)&a[4] = *(const float4*)&As[kk][ty * 8 + 4];
            *(float4*)&b[0] = *(const float4*)&Bs[kk][tx * 4];
#pragma unroll
            for (int i = 0; i < 8; i++)
#pragma unroll
                for (int j = 0; j < 4; j++)
                    acc[i][j] += a[i] * b[j];
        }
        __syncthreads();
    }

#pragma unroll
    for (int i = 0; i < 8; i++) {
        float4 v = make_float4(acc[i][0], acc[i][1], acc[i][2], acc[i][3]);
        *(float4*)&C[(size_t)(row0 + ty * 8 + i) * N + col0 + tx * 4] = v;
    }
}

// ---------------- RMSNorm: dst[row, :len] = x * gamma * rsqrt(mean(x^2)+eps) ----------------
__global__ __launch_bounds__(256) void rmsnorm_kernel(
    const float* __restrict__ src, const float* __restrict__ gamma,
    float* __restrict__ dst, int src_stride, int len)
{
    const int row = blockIdx.x;
    const float* x = src + (size_t)row * src_stride;
    float ss = 0.f;
    for (int i = threadIdx.x; i < len; i += 256) {
        float v = x[i];
        ss += v * v;
    }
#pragma unroll
    for (int off = 16; off; off >>= 1)
        ss += __shfl_xor_sync(0xffffffffu, ss, off);

    __shared__ float warpsum[8];
    __shared__ float s_inv;
    if ((threadIdx.x & 31) == 0) warpsum[threadIdx.x >> 5] = ss;
    __syncthreads();
    if (threadIdx.x == 0) {
        float t = 0.f;
#pragma unroll
        for (int i = 0; i < 8; i++) t += warpsum[i];
        s_inv = rsqrtf(t / (float)len + 1e-6f);
    }
    __syncthreads();
    const float inv = s_inv;
    for (int i = threadIdx.x; i < len; i += 256)
        dst[(size_t)row * len + i] = x[i] * gamma[i] * inv;
}

// ---------------- RoPE + pack into [h][s][d] layouts ----------------
__global__ __launch_bounds__(192) void rope_pack_kernel(
    const float* __restrict__ qp, const float* __restrict__ kvp,
    const float* __restrict__ fused,
    float* __restrict__ Q, float* __restrict__ K, float* __restrict__ V)
{
    const int s = blockIdx.x;
    const int h = blockIdx.y;
    const int d = threadIdx.x;                 // 0..191
    const float scale = 0.07216878364870323f;  // 1/sqrt(192)
    const size_t qbase = ((size_t)h * S + s) * DFULL;

    if (d < DN) {
        float qn = qp[(size_t)s * QB_N + h * DFULL + d];
        float kn = kvp[(size_t)s * KVB_N + h * (DN + DV) + d];
        float vv = kvp[(size_t)s * KVB_N + h * (DN + DV) + DN + d];
        Q[qbase + d] = qn * scale;
        K[qbase + d] = kn;
        V[((size_t)h * S + s) * DV + d] = vv;
    } else {
        int j = d - DN;            // 0..63
        int i = j & 31;
        float inv_freq = powf(10000.f, -(float)(2 * i) / 64.f);
        float ang = (float)s * inv_freq;
        float sn, cs;
        sincosf(ang, &sn, &cs);

        size_t qoff = (size_t)s * QB_N + h * DFULL + DN;
        float qpe = qp[qoff + j];
        float qrot = (j < 32) ? -qp[qoff + j + 32] : qp[qoff + j - 32];

        size_t koff = (size_t)s * FUSED_N + (QL + KL);
        float kpe = fused[koff + j];
        float krot = (j < 32) ? -fused[koff + j + 32] : fused[koff + j - 32];

        Q[qbase + d] = (qpe * cs + qrot * sn) * scale;
        K[qbase + d] = kpe * cs + krot * sn;
    }
}

// ---------------- flash attention (causal), per (qblock, head) ----------------
// 64q x 64k tiles, 256 threads. Smem: Qt[192][64], Kt[192][64], Vs[64][128], Ps[64][65]
#define FLASH_SMEM ((192 * 64 + 192 * 64 + 64 * 128 + 64 * 65) * sizeof(float))

__global__ __launch_bounds__(256) void flash_kernel(
    const float* __restrict__ Q, const float* __restrict__ K,
    const float* __restrict__ V, float* __restrict__ out)
{
    extern __shared__ float sm[];
    float* Qt = sm;                    // [192][64]
    float* Kt = Qt + 192 * 64;         // [192][64]
    float* Vs = Kt + 192 * 64;         // [64][128]
    float* Ps = Vs + 64 * 128;         // [64][65]

    const int qb = blockIdx.x;
    const int h = blockIdx.y;
    const int tid = threadIdx.x;
    const int tx = tid & 15;           // score cols (4), O cols (8)
    const int ty = tid >> 4;           // rows (4)

    const float* Qh = Q + (size_t)h * S * DFULL;
    const float* Kh = K + (size_t)h * S * DFULL;
    const float* Vh = V + (size_t)h * S * DV;

    // stage Q tile transposed
    for (int i = tid; i < 64 * DFULL; i += 256) {
        int r = i / DFULL, d = i % DFULL;
        Qt[d * 64 + r] = Qh[(size_t)(qb * 64 + r) * DFULL + d];
    }

    float m[4], l[4], acc[4][8];
#pragma unroll
    for (int i = 0; i < 4; i++) {
        m[i] = -INFINITY;
        l[i] = 0.f;
#pragma unroll
        for (int j = 0; j < 8; j++) acc[i][j] = 0.f;
    }
    __syncthreads();

    for (int kb = 0; kb <= qb; kb++) {
        for (int i = tid; i < 64 * DFULL; i += 256) {
            int r = i / DFULL, d = i % DFULL;
            Kt[d * 64 + r] = Kh[(size_t)(kb * 64 + r) * DFULL + d];
        }
        for (int i = tid; i < 64 * DV; i += 256)
            Vs[i] = Vh[(size_t)kb * 64 * DV + i];
        __syncthreads();

        // scores 4x4
        float sc[4][4];
#pragma unroll
        for (int i = 0; i < 4; i++)
#pragma unroll
            for (int j = 0; j < 4; j++) sc[i][j] = 0.f;

        for (int d = 0; d < DFULL; d++) {
            float4 a = *(const float4*)&Qt[d * 64 + ty * 4];
            float4 b = *(const float4*)&Kt[d * 64 + tx * 4];
            float av[4] = {a.x, a.y, a.z, a.w};
            float bv[4] = {b.x, b.y, b.z, b.w};
#pragma unroll
            for (int i = 0; i < 4; i++)
#pragma unroll
                for (int j = 0; j < 4; j++)
                    sc[i][j] += av[i] * bv[j];
        }

        if (kb == qb) {
#pragma unroll
            for (int i = 0; i < 4; i++)
#pragma unroll
                for (int j = 0; j < 4; j++)
                    if (tx * 4 + j > ty * 4 + i) sc[i][j] = -INFINITY;
        }

        // online softmax per row (row shared across the 16 tx lanes)
#pragma unroll
        for (int i = 0; i < 4; i++) {
            float mx = fmaxf(fmaxf(sc[i][0], sc[i][1]), fmaxf(sc[i][2], sc[i][3]));
#pragma unroll
            for (int off = 8; off; off >>= 1)
                mx = fmaxf(mx, __shfl_xor_sync(0xffffffffu, mx, off, 16));
            float mnew = fmaxf(m[i], mx);
            float corr = __expf(m[i] - mnew);
            float ls = 0.f;
#pragma unroll
            for (int j = 0; j < 4; j++) {
                float p = __expf(sc[i][j] - mnew);
                sc[i][j] = p;
                ls += p;
            }
#pragma unroll
            for (int off = 8; off; off >>= 1)
                ls += __shfl_xor_sync(0xffffffffu, ls, off, 16);
            l[i] = l[i] * corr + ls;
            m[i] = mnew;
#pragma unroll
            for (int j = 0; j < 8; j++) acc[i][j] *= corr;
#pragma unroll
            for (int j = 0; j < 4; j++)
                Ps[(ty * 4 + i) * 65 + tx * 4 + j] = sc[i][j];
        }
        __syncthreads();

        // O += P @ V   (thread owns rows ty*4..+3, cols tx*8..+7)
        for (int c = 0; c < 64; c++) {
            float p0 = Ps[(ty * 4 + 0) * 65 + c];
            float p1 = Ps[(ty * 4 + 1) * 65 + c];
            float p2 = Ps[(ty * 4 + 2) * 65 + c];
            float p3 = Ps[(ty * 4 + 3) * 65 + c];
            float4 v0 = *(const float4*)&Vs[c * DV + tx * 8];
            float4 v1 = *(const float4*)&Vs[c * DV + tx * 8 + 4];
            float vv[8] = {v0.x, v0.y, v0.z, v0.w, v1.x, v1.y, v1.z, v1.w};
#pragma unroll
            for (int j = 0; j < 8; j++) {
                acc[0][j] += p0 * vv[j];
                acc[1][j] += p1 * vv[j];
                acc[2][j] += p2 * vv[j];
                acc[3][j] += p3 * vv[j];
            }
        }
        __syncthreads();
    }

    // write normalized output: out[s][h*128 + dv]
#pragma unroll
    for (int i = 0; i < 4; i++) {
        float invl = 1.f / l[i];
        int srow = qb * 64 + ty * 4 + i;
        float4 o0 = make_float4(acc[i][0] * invl, acc[i][1] * invl,
                                acc[i][2] * invl, acc[i][3] * invl);
        float4 o1 = make_float4(acc[i][4] * invl, acc[i][5] * invl,
                                acc[i][6] * invl, acc[i][7] * invl);
        *(float4*)&out[(size_t)srow * (NH * DV) + h * DV + tx * 8] = o0;
        *(float4*)&out[(size_t)srow * (NH * DV) + h * DV + tx * 8 + 4] = o1;
    }
}

// ---------------- launcher ----------------
extern "C" void kernel_launch(void* const* d_in, const int* in_sizes, int n_in,
                              void* d_out, int out_size)
{
    const float* hidden     = (const float*)d_in[0];
    const float* w_kv_a     = (const float*)d_in[1];
    const float* q_a_gamma  = (const float*)d_in[2];
    const float* w_qb       = (const float*)d_in[3];
    const float* kv_a_gamma = (const float*)d_in[4];
    const float* w_kvb      = (const float*)d_in[5];
    const float* w_o        = (const float*)d_in[6];
    float* out = (float*)d_out;

    static float *fused = nullptr, *qn, *kvn, *qp, *kvp, *Q, *K, *V, *attn;
    if (!fused) {
        cudaGetSymbolAddress((void**)&fused, g_fused);
        cudaGetSymbolAddress((void**)&qn,    g_qn);
        cudaGetSymbolAddress((void**)&kvn,   g_kvn);
        cudaGetSymbolAddress((void**)&qp,    g_qp);
        cudaGetSymbolAddress((void**)&kvp,   g_kvp);
        cudaGetSymbolAddress((void**)&Q,     g_Q);
        cudaGetSymbolAddress((void**)&K,     g_K);
        cudaGetSymbolAddress((void**)&V,     g_V);
        cudaGetSymbolAddress((void**)&attn,  g_attn);
        cudaFuncSetAttribute(flash_kernel, cudaFuncAttributeMaxDynamicSharedMemorySize,
                             (int)FLASH_SMEM);
    }

    // 1) fused = hidden @ w_kv_a     [2048,2048] x [2048,2112]
    sgemm_128x64<<<dim3(FUSED_N / 64, S / 128), 256>>>(hidden, w_kv_a, fused, S, FUSED_N, Hdim);

    // 2) rmsnorms
    rmsnorm_kernel<<<S, 256>>>(fused, q_a_gamma, qn, FUSED_N, QL);
    rmsnorm_kernel<<<S, 256>>>(fused + QL, kv_a_gamma, kvn, FUSED_N, KL);

    // 3) q = qn @ w_qb               [2048,1536] x [1536,3072]
    sgemm_128x64<<<dim3(QB_N / 64, S / 128), 256>>>(qn, w_qb, qp, S, QB_N, QL);

    // 4) kv = kvn @ w_kvb            [2048,512] x [512,4096]
    sgemm_128x64<<<dim3(KVB_N / 64, S / 128), 256>>>(kvn, w_kvb, kvp, S, KVB_N, KL);

    // 5) rope + pack Q/K/V
    rope_pack_kernel<<<dim3(S, NH), 192>>>(qp, kvp, fused, Q, K, V);

    // 6) causal flash attention
    flash_kernel<<<dim3(S / 64, NH), 256, FLASH_SMEM>>>(Q, K, V, attn);

    // 7) out = attn @ w_o            [2048,2048] x [2048,2048]
    sgemm_128x64<<<dim3(Hdim / 64, S / 128), 256>>>(attn, w_o, out, S, Hdim, NH * DV);
}

// round 3
// speedup vs baseline: 1.0031x; 1.0031x over previous
#include <cuda_runtime.h>
#include <cuda_bf16.h>
#include <math.h>

// ---------------- problem constants ----------------
#define S      2048
#define Hdim   2048
#define NH     16
#define DN     128
#define DR     64
#define DV     128
#define QL     1536
#define KL     512
#define DFULL  (DN + DR)            // 192
#define FUSED_N (QL + KL + DR)      // 2112
#define QB_N   (NH * (DN + DR))     // 3072
#define KVB_N  (NH * (DN + DV))     // 4096

// ---------------- scratch (device globals; no allocation allowed) ----------------
__device__ float g_fused[S * FUSED_N];     // 2048 x 2112
__device__ float g_qn[S * QL];             // rmsnorm(q_c)
__device__ float g_kvn[S * KL];            // rmsnorm(kv_c)
__device__ float g_qp[S * QB_N];           // q projection
__device__ float g_kvp[S * KVB_N];         // kv projection
__device__ float g_Q[NH * S * DFULL];      // [h][s][192], pre-scaled
__device__ float g_K[NH * S * DFULL];      // [h][s][192]
__device__ float g_V[NH * S * DV];         // [h][s][128]
__device__ float g_attn[S * NH * DV];      // [s][h*128+dv]

// ---------------- generic tiled SGEMM: C[M,N] = A[M,K] @ B[K,N] ----------------
// BM=128, BN=64, BK=16, 256 threads (16x16), thread tile 8x4.
// Requires: M%128==0, N%64==0, K%16==0, N%4==0 (all satisfied here).
__global__ __launch_bounds__(256) void sgemm_128x64(
    const float* __restrict__ A, const float* __restrict__ B,
    float* __restrict__ C, int M, int N, int K)
{
    __shared__ float As[16][128];
    __shared__ float Bs[16][64];

    const int tid = threadIdx.x;
    const int tx = tid & 15;       // 0..15 -> 4 cols each
    const int ty = tid >> 4;       // 0..15 -> 8 rows each
    const int row0 = blockIdx.y * 128;
    const int col0 = blockIdx.x * 64;

    float acc[8][4];
#pragma unroll
    for (int i = 0; i < 8; i++)
#pragma unroll
        for (int j = 0; j < 4; j++) acc[i][j] = 0.f;

    for (int k0 = 0; k0 < K; k0 += 16) {
        // load A tile 128x16 (512 float4), store transposed As[k][r]
#pragma unroll
        for (int t = 0; t < 2; t++) {
            int f = tid + t * 256;           // 0..511
            int r = f >> 2;                  // 0..127
            int kc = (f & 3) << 2;           // 0,4,8,12
            float4 va = *(const float4*)&A[(size_t)(row0 + r) * K + k0 + kc];
            As[kc + 0][r] = va.x;
            As[kc + 1][r] = va.y;
            As[kc + 2][r] = va.z;
            As[kc + 3][r] = va.w;
        }
        // load B tile 16x64 (256 float4)
        {
            int r = tid >> 4;                // 0..15
            int c = (tid & 15) << 2;         // 0..60
            *(float4*)&Bs[r][c] = *(const float4*)&B[(size_t)(k0 + r) * N + col0 + c];
        }
        __syncthreads();

#pragma unroll
        for (int kk = 0; kk < 16; kk++) {
            float a[8], b[4];
            *(float4*)&a[0] = *(const float4*)&As[kk][ty * 8];
            *(float4*)&a[4] = *(const float4*)&As[kk][ty * 8 + 4];
            *(float4*)&b[0] = *(const float4*)&Bs[kk][tx * 4];
#pragma unroll
            for (int i = 0; i < 8; i++)
#pragma unroll
                for (int j = 0; j < 4; j++)
                    acc[i][j] += a[i] * b[j];
        }
        __syncthreads();
    }

#pragma unroll
    for (int i = 0; i < 8; i++) {
        float4 v = make_float4(acc[i][0], acc[i][1], acc[i][2], acc[i][3]);
        *(float4*)&C[(size_t)(row0 + ty * 8 + i) * N + col0 + tx * 4] = v;
    }
}

// ---------------- RMSNorm: dst[row, :len] = x * gamma * rsqrt(mean(x^2)+eps) ----------------
__global__ __launch_bounds__(256) void rmsnorm_kernel(
    const float* __restrict__ src, const float* __restrict__ gamma,
    float* __restrict__ dst, int src_stride, int len)
{
    const int row = blockIdx.x;
    const float* x = src + (size_t)row * src_stride;
    float ss = 0.f;
    for (int i = threadIdx.x; i < len; i += 256) {
        float v = x[i];
        ss += v * v;
    }
#pragma unroll
    for (int off = 16; off; off >>= 1)
        ss += __shfl_xor_sync(0xffffffffu, ss, off);

    __shared__ float warpsum[8];
    __shared__ float s_inv;
    if ((threadIdx.x & 31) == 0) warpsum[threadIdx.x >> 5] = ss;
    __syncthreads();
    if (threadIdx.x == 0) {
        float t = 0.f;
#pragma unroll
        for (int i = 0; i < 8; i++) t += warpsum[i];
        s_inv = rsqrtf(t / (float)len + 1e-6f);
    }
    __syncthreads();
    const float inv = s_inv;
    for (int i = threadIdx.x; i < len; i += 256)
        dst[(size_t)row * len + i] = x[i] * gamma[i] * inv;
}

// ---------------- RoPE + pack into [h][s][d] layouts ----------------
__global__ __launch_bounds__(192) void rope_pack_kernel(
    const float* __restrict__ qp, const float* __restrict__ kvp,
    const float* __restrict__ fused,
    float* __restrict__ Q, float* __restrict__ K, float* __restrict__ V)
{
    const int s = blockIdx.x;
    const int h = blockIdx.y;
    const int d = threadIdx.x;                 // 0..191
    const float scale = 0.07216878364870323f;  // 1/sqrt(192)
    const size_t qbase = ((size_t)h * S + s) * DFULL;

    if (d < DN) {
        float qn = qp[(size_t)s * QB_N + h * DFULL + d];
        float kn = kvp[(size_t)s * KVB_N + h * (DN + DV) + d];
        float vv = kvp[(size_t)s * KVB_N + h * (DN + DV) + DN + d];
        Q[qbase + d] = qn * scale;
        K[qbase + d] = kn;
        V[((size_t)h * S + s) * DV + d] = vv;
    } else {
        int j = d - DN;            // 0..63
        int i = j & 31;
        float inv_freq = powf(10000.f, -(float)(2 * i) / 64.f);
        float ang = (float)s * inv_freq;
        float sn, cs;
        sincosf(ang, &sn, &cs);

        size_t qoff = (size_t)s * QB_N + h * DFULL + DN;
        float qpe = qp[qoff + j];
        float qrot = (j < 32) ? -qp[qoff + j + 32] : qp[qoff + j - 32];

        size_t koff = (size_t)s * FUSED_N + (QL + KL);
        float kpe = fused[koff + j];
        float krot = (j < 32) ? -fused[koff + j + 32] : fused[koff + j - 32];

        Q[qbase + d] = (qpe * cs + qrot * sn) * scale;
        K[qbase + d] = kpe * cs + krot * sn;
    }
}

// ---------------- flash attention (causal), per (qblock, head) ----------------
// 64q x 64k tiles, 256 threads. Smem: Qt[192][64], Kt[192][64], Vs[64][128], Ps[64][65]
#define FLASH_SMEM ((192 * 64 + 192 * 64 + 64 * 128 + 64 * 65) * sizeof(float))

__global__ __launch_bounds__(256) void flash_kernel(
    const float* __restrict__ Q, const float* __restrict__ K,
    const float* __restrict__ V, float* __restrict__ out)
{
    extern __shared__ float sm[];
    float* Qt = sm;                    // [192][64]
    float* Kt = Qt + 192 * 64;         // [192][64]
    float* Vs = Kt + 192 * 64;         // [64][128]
    float* Ps = Vs + 64 * 128;         // [64][65]

    const int qb = blockIdx.x;
    const int h = blockIdx.y;
    const int tid = threadIdx.x;
    const int tx = tid & 15;           // score cols (4), O cols (8)
    const int ty = tid >> 4;           // rows (4)

    const float* Qh = Q + (size_t)h * S * DFULL;
    const float* Kh = K + (size_t)h * S * DFULL;
    const float* Vh = V + (size_t)h * S * DV;

    // stage Q tile transposed
    for (int i = tid; i < 64 * DFULL; i += 256) {
        int r = i / DFULL, d = i % DFULL;
        Qt[d * 64 + r] = Qh[(size_t)(qb * 64 + r) * DFULL + d];
    }

    float m[4], l[4], acc[4][8];
#pragma unroll
    for (int i = 0; i < 4; i++) {
        m[i] = -INFINITY;
        l[i] = 0.f;
#pragma unroll
        for (int j = 0; j < 8; j++) acc[i][j] = 0.f;
    }
    __syncthreads();

    for (int kb = 0; kb <= qb; kb++) {
        for (int i = tid; i < 64 * DFULL; i += 256) {
            int r = i / DFULL, d = i % DFULL;
            Kt[d * 64 + r] = Kh[(size_t)(kb * 64 + r) * DFULL + d];
        }
        for (int i = tid; i < 64 * DV; i += 256)
            Vs[i] = Vh[(size_t)kb * 64 * DV + i];
        __syncthreads();

        // scores 4x4
        float sc[4][4];
#pragma unroll
        for (int i = 0; i < 4; i++)
#pragma unroll
            for (int j = 0; j < 4; j++) sc[i][j] = 0.f;

        for (int d = 0; d < DFULL; d++) {
            float4 a = *(const float4*)&Qt[d * 64 + ty * 4];
            float4 b = *(const float4*)&Kt[d * 64 + tx * 4];
            float av[4] = {a.x, a.y, a.z, a.w};
            float bv[4] = {b.x, b.y, b.z, b.w};
#pragma unroll
            for (int i = 0; i < 4; i++)
#pragma unroll
                for (int j = 0; j < 4; j++)
                    sc[i][j] += av[i] * bv[j];
        }

        if (kb == qb) {
#pragma unroll
            for (int i = 0; i < 4; i++)
#pragma unroll
                for (int j = 0; j < 4; j++)
                    if (tx * 4 + j > ty * 4 + i) sc[i][j] = -INFINITY;
        }

        // online softmax per row (row shared across the 16 tx lanes)
#pragma unroll
        for (int i = 0; i < 4; i++) {
            float mx = fmaxf(fmaxf(sc[i][0], sc[i][1]), fmaxf(sc[i][2], sc[i][3]));
#pragma unroll
            for (int off = 8; off; off >>= 1)
                mx = fmaxf(mx, __shfl_xor_sync(0xffffffffu, mx, off, 16));
            float mnew = fmaxf(m[i], mx);
            float corr = __expf(m[i] - mnew);
            float ls = 0.f;
#pragma unroll
            for (int j = 0; j < 4; j++) {
                float p = __expf(sc[i][j] - mnew);
                sc[i][j] = p;
                ls += p;
            }
#pragma unroll
            for (int off = 8; off; off >>= 1)
                ls += __shfl_xor_sync(0xffffffffu, ls, off, 16);
            l[i] = l[i] * corr + ls;
            m[i] = mnew;
#pragma unroll
            for (int j = 0; j < 8; j++) acc[i][j] *= corr;
#pragma unroll
            for (int j = 0; j < 4; j++)
                Ps[(ty * 4 + i) * 65 + tx * 4 + j] = sc[i][j];
        }
        __syncthreads();

        // O += P @ V   (thread owns rows ty*4..+3, cols tx*8..+7)
        for (int c = 0; c < 64; c++) {
            float p0 = Ps[(ty * 4 + 0) * 65 + c];
            float p1 = Ps[(ty * 4 + 1) * 65 + c];
            float p2 = Ps[(ty * 4 + 2) * 65 + c];
            float p3 = Ps[(ty * 4 + 3) * 65 + c];
            float4 v0 = *(const float4*)&Vs[c * DV + tx * 8];
            float4 v1 = *(const float4*)&Vs[c * DV + tx * 8 + 4];
            float vv[8] = {v0.x, v0.y, v0.z, v0.w, v1.x, v1.y, v1.z, v1.w};
#pragma unroll
            for (int j = 0; j < 8; j++) {
                acc[0][j] += p0 * vv[j];
                acc[1][j] += p1 * vv[j];
                acc[2][j] += p2 * vv[j];
                acc[3][j] += p3 * vv[j];
            }
        }
        __syncthreads();
    }

    // write normalized output: out[s][h*128 + dv]
#pragma unroll
    for (int i = 0; i < 4; i++) {
        float invl = 1.f / l[i];
        int srow = qb * 64 + ty * 4 + i;
        float4 o0 = make_float4(acc[i][0] * invl, acc[i][1] * invl,
                                acc[i][2] * invl, acc[i][3] * invl);
        float4 o1 = make_float4(acc[i][4] * invl, acc[i][5] * invl,
                                acc[i][6] * invl, acc[i][7] * invl);
        *(float4*)&out[(size_t)srow * (NH * DV) + h * DV + tx * 8] = o0;
        *(float4*)&out[(size_t)srow * (NH * DV) + h * DV + tx * 8 + 4] = o1;
    }
}

// ---------------- launcher ----------------
extern "C" void kernel_launch(void* const* d_in, const int* in_sizes, int n_in,
                              void* d_out, int out_size)
{
    const float* hidden     = (const float*)d_in[0];
    const float* w_kv_a     = (const float*)d_in[1];
    const float* q_a_gamma  = (const float*)d_in[2];
    const float* w_qb       = (const float*)d_in[3];
    const float* kv_a_gamma = (const float*)d_in[4];
    const float* w_kvb      = (const float*)d_in[5];
    const float* w_o        = (const float*)d_in[6];
    float* out = (float*)d_out;

    static float *fused = nullptr, *qn, *kvn, *qp, *kvp, *Q, *K, *V, *attn;
    if (!fused) {
        cudaGetSymbolAddress((void**)&fused, g_fused);
        cudaGetSymbolAddress((void**)&qn,    g_qn);
        cudaGetSymbolAddress((void**)&kvn,   g_kvn);
        cudaGetSymbolAddress((void**)&qp,    g_qp);
        cudaGetSymbolAddress((void**)&kvp,   g_kvp);
        cudaGetSymbolAddress((void**)&Q,     g_Q);
        cudaGetSymbolAddress((void**)&K,     g_K);
        cudaGetSymbolAddress((void**)&V,     g_V);
        cudaGetSymbolAddress((void**)&attn,  g_attn);
        cudaFuncSetAttribute(flash_kernel, cudaFuncAttributeMaxDynamicSharedMemorySize,
                             (int)FLASH_SMEM);
    }

    // 1) fused = hidden @ w_kv_a     [2048,2048] x [2048,2112]
    sgemm_128x64<<<dim3(FUSED_N / 64, S / 128), 256>>>(hidden, w_kv_a, fused, S, FUSED_N, Hdim);

    // 2) rmsnorms
    rmsnorm_kernel<<<S, 256>>>(fused, q_a_gamma, qn, FUSED_N, QL);
    rmsnorm_kernel<<<S, 256>>>(fused + QL, kv_a_gamma, kvn, FUSED_N, KL);

    // 3) q = qn @ w_qb               [2048,1536] x [1536,3072]
    sgemm_128x64<<<dim3(QB_N / 64, S / 128), 256>>>(qn, w_qb, qp, S, QB_N, QL);

    // 4) kv = kvn @ w_kvb            [2048,512] x [512,4096]
    sgemm_128x64<<<dim3(KVB_N / 64, S / 128), 256>>>(kvn, w_kvb, kvp, S, KVB_N, KL);

    // 5) rope + pack Q/K/V
    rope_pack_kernel<<<dim3(S, NH), 192>>>(qp, kvp, fused, Q, K, V);

    // 6) causal flash attention
    flash_kernel<<<dim3(S / 64, NH), 256, FLASH_SMEM>>>(Q, K, V, attn);

    // 7) out = attn @ w_o            [2048,2048] x [2048,2048]
    sgemm_128x64<<<dim3(Hdim / 64, S / 128), 256>>>(attn, w_o, out, S, Hdim, NH * DV);
}

// round 5
// speedup vs baseline: 1.9382x; 1.9323x over previous
#include <cuda_runtime.h>
#include <cuda_bf16.h>
#include <math.h>
#include <stdint.h>

#define SEQ    2048
#define HDIM   2048
#define NH     16
#define DN     128
#define DR     64
#define DV     128
#define QL     1536
#define KL     512
#define DFULL  192
#define FUSED_NPAD 2176
#define FUSED_REAL 2112
#define QB_N   3072
#define KVB_N  4096

// ---------------- device scratch (zero-initialized globals) ----------------
__device__ float g_fused[SEQ * FUSED_NPAD];
__device__ float g_qn[SEQ * QL];
__device__ float g_kvn[SEQ * KL];
__device__ float g_qp[SEQ * QB_N];
__device__ float g_kvp[SEQ * KVB_N];
__device__ float g_Qf[NH * SEQ * DFULL];
__device__ float g_Kf[NH * SEQ * DFULL];
__device__ float g_Vt[NH * DV * SEQ];        // [h][d][s]
__device__ float g_Sc[NH * SEQ * SEQ];
__device__ float g_P [NH * SEQ * SEQ];       // tail (k>q) stays 0 forever
__device__ float g_attn[SEQ * NH * DV];
__device__ float g_WkvaT[FUSED_NPAD * HDIM]; // rows >= 2112 stay 0
__device__ float g_WqbT [QB_N * QL];
__device__ float g_WkvbT[KVB_N * KL];
__device__ float g_WoT  [HDIM * HDIM];

// ---------------- bf16 split helper ----------------
__device__ __forceinline__ void bf_split(float x, __nv_bfloat16& hi, __nv_bfloat16& lo) {
    hi = __float2bfloat16(x);
    lo = __float2bfloat16(x - __bfloat162float(hi));
}

__device__ __forceinline__ void mma16816(float* c, const uint32_t* a, const uint32_t* b) {
    asm volatile(
        "mma.sync.aligned.m16n8k16.row.col.f32.bf16.bf16.f32 "
        "{%0,%1,%2,%3}, {%4,%5,%6,%7}, {%8,%9}, {%0,%1,%2,%3};"
        : "+f"(c[0]), "+f"(c[1]), "+f"(c[2]), "+f"(c[3])
        : "r"(a[0]), "r"(a[1]), "r"(a[2]), "r"(a[3]), "r"(b[0]), "r"(b[1]));
}

// ============================================================================
// GEMM via mma.sync bf16 + in-kernel Markidis split (3 passes -> ~fp32 accuracy)
// C[m,n] = sum_k A[m,k] * B[n,k];  A [M,K] row-major fp32, B [N,K] fp32.
// Tile 128x128, BK=32, 256 threads (8 warps, 2m x 4n, warp tile 64x32).
// mode 0: plain; 1: skip blocks with n0 > m0+127; 2: k limited to < m0+128.
// ============================================================================
#define BKG 32
#define SKH 40   // smem half-stride per row

__global__ __launch_bounds__(256) void gemm_mma(
    const float* __restrict__ A, long long sA,
    const float* __restrict__ B, long long sB,
    float* __restrict__ C, long long sC,
    int lda, int ldb, int ldc, int K, int mode)
{
    const int n0 = blockIdx.x * 128;
    const int m0 = blockIdx.y * 128;
    if (mode == 1 && n0 > m0 + 127) return;
    A += (size_t)blockIdx.z * sA;
    B += (size_t)blockIdx.z * sB;
    C += (size_t)blockIdx.z * sC;

    int kend = K;
    if (mode == 2 && m0 + 128 < kend) kend = m0 + 128;

    __shared__ __nv_bfloat16 Ah[128 * SKH], Al[128 * SKH];
    __shared__ __nv_bfloat16 Bh[128 * SKH], Bl[128 * SKH];

    const int tid = threadIdx.x;
    const int lane = tid & 31;
    const int wid = tid >> 5;
    const int wm = (wid & 1) * 64;   // warp row offset
    const int wn = (wid >> 1) * 32;  // warp col offset
    const int g = lane >> 2;         // group id 0..7
    const int t4 = lane & 3;         // 0..3

    float c[4][4][4];
#pragma unroll
    for (int i = 0; i < 4; i++)
#pragma unroll
        for (int j = 0; j < 4; j++)
#pragma unroll
            for (int e = 0; e < 4; e++) c[i][j][e] = 0.f;

    for (int k0 = 0; k0 < kend; k0 += BKG) {
        __syncthreads();
        // stage A & B tiles (fp32 -> hi/lo bf16)
#pragma unroll
        for (int i = 0; i < 4; i++) {
            int idx = tid + i * 256;            // 0..1023
            int r = idx >> 3;                   // 0..127
            int kw = (idx & 7) << 2;            // 0,4,...,28
            float4 va = *(const float4*)&A[(size_t)(m0 + r) * lda + k0 + kw];
            float4 vb = *(const float4*)&B[(size_t)(n0 + r) * ldb + k0 + kw];
            float av[4] = {va.x, va.y, va.z, va.w};
            float bv[4] = {vb.x, vb.y, vb.z, vb.w};
#pragma unroll
            for (int j = 0; j < 4; j++) {
                __nv_bfloat16 hi, lo;
                bf_split(av[j], hi, lo);
                Ah[r * SKH + kw + j] = hi;
                Al[r * SKH + kw + j] = lo;
                bf_split(bv[j], hi, lo);
                Bh[r * SKH + kw + j] = hi;
                Bl[r * SKH + kw + j] = lo;
            }
        }
        __syncthreads();

#pragma unroll
        for (int kc = 0; kc < 2; kc++) {
            const int ck = kc * 16 + t4 * 2;
            uint32_t ah[4][4], al[4][4], bh[4][2], bl[4][2];
#pragma unroll
            for (int mt = 0; mt < 4; mt++) {
                int r = wm + mt * 16 + g;
                ah[mt][0] = *(const uint32_t*)&Ah[r * SKH + ck];
                ah[mt][1] = *(const uint32_t*)&Ah[(r + 8) * SKH + ck];
                ah[mt][2] = *(const uint32_t*)&Ah[r * SKH + ck + 8];
                ah[mt][3] = *(const uint32_t*)&Ah[(r + 8) * SKH + ck + 8];
                al[mt][0] = *(const uint32_t*)&Al[r * SKH + ck];
                al[mt][1] = *(const uint32_t*)&Al[(r + 8) * SKH + ck];
                al[mt][2] = *(const uint32_t*)&Al[r * SKH + ck + 8];
                al[mt][3] = *(const uint32_t*)&Al[(r + 8) * SKH + ck + 8];
            }
#pragma unroll
            for (int nt = 0; nt < 4; nt++) {
                int n = wn + nt * 8 + g;
                bh[nt][0] = *(const uint32_t*)&Bh[n * SKH + ck];
                bh[nt][1] = *(const uint32_t*)&Bh[n * SKH + ck + 8];
                bl[nt][0] = *(const uint32_t*)&Bl[n * SKH + ck];
                bl[nt][1] = *(const uint32_t*)&Bl[n * SKH + ck + 8];
            }
#pragma unroll
            for (int mt = 0; mt < 4; mt++)
#pragma unroll
                for (int nt = 0; nt < 4; nt++) {
                    mma16816(c[mt][nt], ah[mt], bh[nt]);   // hi*hi
                    mma16816(c[mt][nt], ah[mt], bl[nt]);   // hi*lo
                    mma16816(c[mt][nt], al[mt], bh[nt]);   // lo*hi
                }
        }
    }

    // epilogue
#pragma unroll
    for (int mt = 0; mt < 4; mt++) {
#pragma unroll
        for (int nt = 0; nt < 4; nt++) {
            int row = m0 + wm + mt * 16 + g;
            int col = n0 + wn + nt * 8 + t4 * 2;
            *(float2*)&C[(size_t)row * ldc + col] =
                make_float2(c[mt][nt][0], c[mt][nt][1]);
            *(float2*)&C[(size_t)(row + 8) * ldc + col] =
                make_float2(c[mt][nt][2], c[mt][nt][3]);
        }
    }
}

// ---------------- weight transpose: W[K,N] -> Wt[N,K] ----------------
__global__ __launch_bounds__(1024) void transpose_w(
    const float* __restrict__ W, float* __restrict__ Wt, int K, int N)
{
    __shared__ float t[32][33];
    const int kb = blockIdx.x * 32, nb = blockIdx.y * 32;
    const int tx = threadIdx.x & 31, ty = threadIdx.x >> 5;
    t[ty][tx] = W[(size_t)(kb + ty) * N + nb + tx];
    __syncthreads();
    Wt[(size_t)(nb + ty) * K + kb + tx] = t[tx][ty];
}

// ---------------- RMSNorm ----------------
__global__ __launch_bounds__(256) void rmsnorm_k(
    const float* __restrict__ src, const float* __restrict__ gamma,
    float* __restrict__ dst, int stride, int len)
{
    const int row = blockIdx.x;
    const float* x = src + (size_t)row * stride;
    float ss = 0.f;
    for (int i = threadIdx.x; i < len; i += 256) { float v = x[i]; ss += v * v; }
#pragma unroll
    for (int o = 16; o; o >>= 1) ss += __shfl_xor_sync(0xffffffffu, ss, o);
    __shared__ float ws[8]; __shared__ float s_inv;
    if ((threadIdx.x & 31) == 0) ws[threadIdx.x >> 5] = ss;
    __syncthreads();
    if (threadIdx.x == 0) {
        float t = 0.f;
#pragma unroll
        for (int i = 0; i < 8; i++) t += ws[i];
        s_inv = rsqrtf(t / (float)len + 1e-6f);
    }
    __syncthreads();
    const float inv = s_inv;
    for (int i = threadIdx.x; i < len; i += 256)
        dst[(size_t)row * len + i] = x[i] * gamma[i] * inv;
}

// ---------------- RoPE + pack (fp32) ----------------
__global__ __launch_bounds__(192) void rope_pack(
    const float* __restrict__ qp, const float* __restrict__ kvp,
    const float* __restrict__ fused,
    float* __restrict__ Qf, float* __restrict__ Kf, float* __restrict__ Vt)
{
    const int s = blockIdx.x, h = blockIdx.y, d = threadIdx.x;
    const float scale = 0.07216878364870323f;  // 1/sqrt(192)
    const size_t qbase = ((size_t)h * SEQ + s) * DFULL;
    if (d < DN) {
        Qf[qbase + d] = qp[(size_t)s * QB_N + h * DFULL + d] * scale;
        Kf[qbase + d] = kvp[(size_t)s * KVB_N + h * (DN + DV) + d];
        Vt[((size_t)h * DV + d) * SEQ + s] = kvp[(size_t)s * KVB_N + h * (DN + DV) + DN + d];
    } else {
        int j = d - DN, i = j & 31;
        float inv_freq = powf(10000.f, -(float)(2 * i) / 64.f);
        float sn, cs;
        sincosf((float)s * inv_freq, &sn, &cs);
        size_t qoff = (size_t)s * QB_N + h * DFULL + DN;
        float qpe = qp[qoff + j];
        float qrot = (j < 32) ? -qp[qoff + j + 32] : qp[qoff + j - 32];
        size_t koff = (size_t)s * FUSED_NPAD + (QL + KL);
        float kpe = fused[koff + j];
        float krot = (j < 32) ? -fused[koff + j + 32] : fused[koff + j - 32];
        Qf[qbase + d] = (qpe * cs + qrot * sn) * scale;
        Kf[qbase + d] = kpe * cs + krot * sn;
    }
}

// ---------------- causal softmax (fp32 out; tail k>q never written) ----------------
__global__ __launch_bounds__(256) void softmax_k(
    const float* __restrict__ Sc, float* __restrict__ P)
{
    const int q = blockIdx.x, h = blockIdx.y, tid = threadIdx.x;
    const float* row = Sc + ((size_t)h * SEQ + q) * SEQ;
    float* out = P + ((size_t)h * SEQ + q) * SEQ;
    const int n = q + 1;
    __shared__ float red[8]; __shared__ float bc;

    float mx = -INFINITY;
    for (int i = tid; i < n; i += 256) mx = fmaxf(mx, row[i]);
#pragma unroll
    for (int o = 16; o; o >>= 1) mx = fmaxf(mx, __shfl_xor_sync(0xffffffffu, mx, o));
    if ((tid & 31) == 0) red[tid >> 5] = mx;
    __syncthreads();
    if (tid == 0) {
        float m = red[0];
#pragma unroll
        for (int i = 1; i < 8; i++) m = fmaxf(m, red[i]);
        bc = m;
    }
    __syncthreads();
    const float M = bc;
    float sm = 0.f;
    for (int i = tid; i < n; i += 256) sm += __expf(row[i] - M);
#pragma unroll
    for (int o = 16; o; o >>= 1) sm += __shfl_xor_sync(0xffffffffu, sm, o);
    if ((tid & 31) == 0) red[tid >> 5] = sm;
    __syncthreads();
    if (tid == 0) {
        float t = 0.f;
#pragma unroll
        for (int i = 0; i < 8; i++) t += red[i];
        bc = 1.f / t;
    }
    __syncthreads();
    const float inv = bc;
    for (int i = tid; i < n; i += 256)
        out[i] = __expf(row[i] - M) * inv;
}

// ---------------- launcher ----------------
extern "C" void kernel_launch(void* const* d_in, const int* in_sizes, int n_in,
                              void* d_out, int out_size)
{
    const float* hidden     = (const float*)d_in[0];
    const float* w_kv_a     = (const float*)d_in[1];
    const float* q_a_gamma  = (const float*)d_in[2];
    const float* w_qb       = (const float*)d_in[3];
    const float* kv_a_gamma = (const float*)d_in[4];
    const float* w_kvb      = (const float*)d_in[5];
    const float* w_o        = (const float*)d_in[6];
    float* out = (float*)d_out;

    static float *fused = nullptr, *qn, *kvn, *qp, *kvp, *Qf, *Kf, *Vt, *Sc, *P, *attn;
    static float *WkvaT, *WqbT, *WkvbT, *WoT;
    if (!fused) {
        cudaGetSymbolAddress((void**)&fused, g_fused);
        cudaGetSymbolAddress((void**)&qn,    g_qn);
        cudaGetSymbolAddress((void**)&kvn,   g_kvn);
        cudaGetSymbolAddress((void**)&qp,    g_qp);
        cudaGetSymbolAddress((void**)&kvp,   g_kvp);
        cudaGetSymbolAddress((void**)&Qf,    g_Qf);
        cudaGetSymbolAddress((void**)&Kf,    g_Kf);
        cudaGetSymbolAddress((void**)&Vt,    g_Vt);
        cudaGetSymbolAddress((void**)&Sc,    g_Sc);
        cudaGetSymbolAddress((void**)&P,     g_P);
        cudaGetSymbolAddress((void**)&attn,  g_attn);
        cudaGetSymbolAddress((void**)&WkvaT, g_WkvaT);
        cudaGetSymbolAddress((void**)&WqbT,  g_WqbT);
        cudaGetSymbolAddress((void**)&WkvbT, g_WkvbT);
        cudaGetSymbolAddress((void**)&WoT,   g_WoT);
    }

    // weight transposes (W[K,N] -> Wt[N,K]); pad rows of WkvaT stay zero
    transpose_w<<<dim3(HDIM / 32, FUSED_REAL / 32), 1024>>>(w_kv_a, WkvaT, HDIM, FUSED_REAL);
    transpose_w<<<dim3(QL / 32, QB_N / 32), 1024>>>(w_qb, WqbT, QL, QB_N);
    transpose_w<<<dim3(KL / 32, KVB_N / 32), 1024>>>(w_kvb, WkvbT, KL, KVB_N);
    transpose_w<<<dim3(HDIM / 32, HDIM / 32), 1024>>>(w_o, WoT, HDIM, HDIM);

    // 1) fused = hidden @ w_kv_a
    gemm_mma<<<dim3(FUSED_NPAD / 128, SEQ / 128), 256>>>(
        hidden, 0, WkvaT, 0, fused, 0, HDIM, HDIM, FUSED_NPAD, HDIM, 0);

    // 2) rmsnorms
    rmsnorm_k<<<SEQ, 256>>>(fused, q_a_gamma, qn, FUSED_NPAD, QL);
    rmsnorm_k<<<SEQ, 256>>>(fused + QL, kv_a_gamma, kvn, FUSED_NPAD, KL);

    // 3) projections
    gemm_mma<<<dim3(QB_N / 128, SEQ / 128), 256>>>(
        qn, 0, WqbT, 0, qp, 0, QL, QL, QB_N, QL, 0);
    gemm_mma<<<dim3(KVB_N / 128, SEQ / 128), 256>>>(
        kvn, 0, WkvbT, 0, kvp, 0, KL, KL, KVB_N, KL, 0);

    // 4) rope + pack
    rope_pack<<<dim3(SEQ, NH), 192>>>(qp, kvp, fused, Qf, Kf, Vt);

    // 5) scores = Q @ K^T (causal block-skip), per head
    gemm_mma<<<dim3(SEQ / 128, SEQ / 128, NH), 256>>>(
        Qf, (long long)SEQ * DFULL, Kf, (long long)SEQ * DFULL,
        Sc, (long long)SEQ * SEQ, DFULL, DFULL, SEQ, DFULL, 1);

    // 6) softmax
    softmax_k<<<dim3(SEQ, NH), 256>>>(Sc, P);

    // 7) attn = P @ V (causal k-limit), per head
    gemm_mma<<<dim3(1, SEQ / 128, NH), 256>>>(
        P, (long long)SEQ * SEQ, Vt, (long long)DV * SEQ,
        attn, (long long)DV, SEQ, SEQ, NH * DV, SEQ, 2);

    // 8) out = attn @ w_o
    gemm_mma<<<dim3(HDIM / 128, SEQ / 128), 256>>>(
        attn, 0, WoT, 0, out, 0, HDIM, HDIM, HDIM, HDIM, 0);
}

// round 6
// speedup vs baseline: 2.8841x; 1.4881x over previous
#include <cuda_runtime.h>
#include <cuda_bf16.h>
#include <math.h>
#include <stdint.h>

#define SEQ    2048
#define HDIM   2048
#define NH     16
#define DN     128
#define DR     64
#define DV     128
#define QL     1536
#define KL     512
#define DFULL  192
#define FUSED_NPAD 2176
#define FUSED_REAL 2112
#define QB_N   3072
#define KVB_N  4096
#define KP_H   6144
#define KP_QL  4608
#define KP_KL  1536
#define KP_D   576
#define KP_SEQ 6144

// ---------------- device scratch (zero-initialized) ----------------
__device__ float g_fused[SEQ * FUSED_NPAD];
__device__ float g_qp[SEQ * QB_N];
__device__ float g_kvp[SEQ * KVB_N];
__device__ float g_Sc[NH * SEQ * SEQ];
__device__ float g_attn[SEQ * HDIM];
__device__ __nv_bfloat16 g_H3   [SEQ * KP_H];
__device__ __nv_bfloat16 g_QN3  [SEQ * KP_QL];
__device__ __nv_bfloat16 g_KVN3 [SEQ * KP_KL];
__device__ __nv_bfloat16 g_ATTN3[SEQ * KP_H];
__device__ __nv_bfloat16 g_WKVA3[FUSED_NPAD * KP_H];   // rows >= 2112 stay 0
__device__ __nv_bfloat16 g_WQB3 [QB_N * KP_QL];
__device__ __nv_bfloat16 g_WKVB3[KVB_N * KP_KL];
__device__ __nv_bfloat16 g_WO3  [HDIM * KP_H];
__device__ __nv_bfloat16 g_Q3 [NH * SEQ * KP_D];
__device__ __nv_bfloat16 g_K3 [NH * SEQ * KP_D];
__device__ __nv_bfloat16 g_V3 [NH * DV * KP_SEQ];      // [h][d][3s]
__device__ __nv_bfloat16 g_P3 [NH * SEQ * KP_SEQ];     // tail (k>q) stays 0

// ---------------- helpers ----------------
__device__ __forceinline__ void bf_split(float x, __nv_bfloat16& hi, __nv_bfloat16& lo) {
    hi = __float2bfloat16(x);
    lo = __float2bfloat16(x - __bfloat162float(hi));
}
__device__ __forceinline__ uint32_t smem_u32(const void* p) {
    uint32_t a;
    asm("{ .reg .u64 t; cvta.to.shared.u64 t, %1; cvt.u32.u64 %0, t; }" : "=r"(a) : "l"(p));
    return a;
}
__device__ __forceinline__ void cp16(uint32_t dst, const void* src) {
    asm volatile("cp.async.cg.shared.global [%0], [%1], 16;" :: "r"(dst), "l"(src));
}
__device__ __forceinline__ void ldsm_x4(uint32_t* r, uint32_t a) {
    asm volatile("ldmatrix.sync.aligned.m8n8.x4.shared.b16 {%0,%1,%2,%3}, [%4];"
                 : "=r"(r[0]), "=r"(r[1]), "=r"(r[2]), "=r"(r[3]) : "r"(a));
}
__device__ __forceinline__ void ldsm_x2(uint32_t* r, uint32_t a) {
    asm volatile("ldmatrix.sync.aligned.m8n8.x2.shared.b16 {%0,%1}, [%2];"
                 : "=r"(r[0]), "=r"(r[1]) : "r"(a));
}
__device__ __forceinline__ void mma16816(float* c, const uint32_t* a, const uint32_t* b) {
    asm volatile(
        "mma.sync.aligned.m16n8k16.row.col.f32.bf16.bf16.f32 "
        "{%0,%1,%2,%3}, {%4,%5,%6,%7}, {%8,%9}, {%0,%1,%2,%3};"
        : "+f"(c[0]), "+f"(c[1]), "+f"(c[2]), "+f"(c[3])
        : "r"(a[0]), "r"(a[1]), "r"(a[2]), "r"(a[3]), "r"(b[0]), "r"(b[1]));
}

// ============================================================================
// bf16 GEMM: C[m,n] = sum_k' A[m,k'] B[n,k'] (both K'-major bf16, C fp32)
// Tile 128x128, BK'=64, 256 threads, cp.async double-buffer, ldmatrix.
// mode 0: plain; 1: skip n0 > m0+127; 2: k'-tiles limited to 3*(m0+128).
// ============================================================================
#define GSMEM 65536

__global__ __launch_bounds__(256) void gemm_bf16(
    const __nv_bfloat16* __restrict__ A, long long sA,
    const __nv_bfloat16* __restrict__ B, long long sB,
    float* __restrict__ C, long long sC,
    int lda, int ldb, int ldc, int Kp, int mode)
{
    const int n0 = blockIdx.x * 128;
    const int m0 = blockIdx.y * 128;
    if (mode == 1 && n0 > m0 + 127) return;
    A += (size_t)blockIdx.z * sA;
    B += (size_t)blockIdx.z * sB;
    C += (size_t)blockIdx.z * sC;

    int ntiles = Kp >> 6;
    if (mode == 2) {
        int lim = (3 * (m0 + 128)) >> 6;
        if (lim < ntiles) ntiles = lim;
    }

    extern __shared__ char smraw[];
    const uint32_t sA0 = smem_u32(smraw);            // A: [2][16KB]
    const uint32_t sB0 = sA0 + 32768;                // B: [2][16KB]

    const int tid = threadIdx.x;
    const int lane = tid & 31;
    const int wid = tid >> 5;
    const int wm = (wid & 1) * 64;
    const int wn = (wid >> 1) * 32;
    const int l7 = lane & 7;
    const int g = lane >> 2, t4 = lane & 3;

    // ldmatrix per-lane row offsets (bytes; row stride 128B)
    const int ra = lane & 15;              // A row within 16-row tile
    const int sega = (lane >> 4) & 1;      // A k-seg select
    const int lb = lane & 15;
    const int rb = lb & 7;                 // B row within 8-row tile
    const int segb = (lb >> 3) & 1;
    uint32_t a_off[4], b_off[4];
#pragma unroll
    for (int mt = 0; mt < 4; mt++) a_off[mt] = (uint32_t)((wm + mt * 16 + ra) * 128);
#pragma unroll
    for (int nt = 0; nt < 4; nt++) b_off[nt] = (uint32_t)((wn + nt * 8 + rb) * 128);

    float c[4][4][4];
#pragma unroll
    for (int i = 0; i < 4; i++)
#pragma unroll
        for (int j = 0; j < 4; j++)
#pragma unroll
            for (int e = 0; e < 4; e++) c[i][j][e] = 0.f;

    // ---- async tile loader (one commit group per tile) ----
    auto load_tile = [&](int i, int buf) {
        const __nv_bfloat16* Ag = A + (size_t)m0 * lda + (i << 6);
        const __nv_bfloat16* Bg = B + (size_t)n0 * ldb + (i << 6);
        const uint32_t da = sA0 + buf * 16384;
        const uint32_t db = sB0 + buf * 16384;
#pragma unroll
        for (int t = 0; t < 4; t++) {
            int ch = tid + t * 256;               // 0..1023
            int r = ch >> 3;                      // row 0..127
            int s = ch & 7;                       // 16B seg 0..7
            uint32_t sw = (uint32_t)(r * 128 + ((s ^ (r & 7)) << 4));
            cp16(da + sw, Ag + (size_t)r * lda + s * 8);
            cp16(db + sw, Bg + (size_t)r * ldb + s * 8);
        }
        asm volatile("cp.async.commit_group;");
    };

    load_tile(0, 0);
    for (int i = 0; i < ntiles; i++) {
        const int cur = i & 1;
        if (i + 1 < ntiles) {
            load_tile(i + 1, cur ^ 1);
            asm volatile("cp.async.wait_group 1;");
        } else {
            asm volatile("cp.async.wait_group 0;");
        }
        __syncthreads();

        const uint32_t ab = sA0 + cur * 16384;
        const uint32_t bb = sB0 + cur * 16384;
#pragma unroll
        for (int kc = 0; kc < 4; kc++) {
            const uint32_t ax = (uint32_t)(((kc * 2 + sega) ^ l7) << 4);
            const uint32_t bx = (uint32_t)(((kc * 2 + segb) ^ l7) << 4);
            uint32_t a[4][4], b[4][2];
#pragma unroll
            for (int mt = 0; mt < 4; mt++) ldsm_x4(a[mt], ab + a_off[mt] + ax);
#pragma unroll
            for (int nt = 0; nt < 4; nt++) ldsm_x2(b[nt], bb + b_off[nt] + bx);
#pragma unroll
            for (int mt = 0; mt < 4; mt++)
#pragma unroll
                for (int nt = 0; nt < 4; nt++)
                    mma16816(c[mt][nt], a[mt], b[nt]);
        }
        __syncthreads();
    }

    // epilogue
#pragma unroll
    for (int mt = 0; mt < 4; mt++)
#pragma unroll
        for (int nt = 0; nt < 4; nt++) {
            int row = m0 + wm + mt * 16 + g;
            int col = n0 + wn + nt * 8 + t4 * 2;
            *(float2*)&C[(size_t)row * ldc + col] = make_float2(c[mt][nt][0], c[mt][nt][1]);
            *(float2*)&C[(size_t)(row + 8) * ldc + col] = make_float2(c[mt][nt][2], c[mt][nt][3]);
        }
}

// ---------------- activation split (A-side: hi,hi,lo) ----------------
__global__ __launch_bounds__(256) void split_act(
    const float* __restrict__ X, __nv_bfloat16* __restrict__ X3, int total)
{
    int i = blockIdx.x * 256 + threadIdx.x;
    if (i >= total) return;
    __nv_bfloat16 hi, lo;
    bf_split(X[i], hi, lo);
    __nv_bfloat16* o = X3 + 3 * (size_t)i;
    o[0] = hi; o[1] = hi; o[2] = lo;
}

// ---------------- weight transpose+split: W[K,N] -> W3t[N][3K] (B-side: hi,lo,hi) ----------------
__global__ __launch_bounds__(1024) void transpose_split_w(
    const float* __restrict__ W, __nv_bfloat16* __restrict__ W3t, int K, int N)
{
    __shared__ float t[32][33];
    const int kb = blockIdx.x * 32, nb = blockIdx.y * 32;
    const int tx = threadIdx.x & 31, ty = threadIdx.x >> 5;
    t[ty][tx] = W[(size_t)(kb + ty) * N + nb + tx];
    __syncthreads();
    __nv_bfloat16 hi, lo;
    bf_split(t[tx][ty], hi, lo);
    __nv_bfloat16* o = W3t + (size_t)(nb + ty) * (3 * K) + 3 * (kb + tx);
    o[0] = hi; o[1] = lo; o[2] = hi;
}

// ---------------- RMSNorm + split (A-side) ----------------
__global__ __launch_bounds__(256) void rmsnorm_split(
    const float* __restrict__ src, const float* __restrict__ gamma,
    __nv_bfloat16* __restrict__ dst3, int stride, int len)
{
    const int row = blockIdx.x;
    const float* x = src + (size_t)row * stride;
    float ss = 0.f;
    for (int i = threadIdx.x; i < len; i += 256) { float v = x[i]; ss += v * v; }
#pragma unroll
    for (int o = 16; o; o >>= 1) ss += __shfl_xor_sync(0xffffffffu, ss, o);
    __shared__ float ws[8]; __shared__ float s_inv;
    if ((threadIdx.x & 31) == 0) ws[threadIdx.x >> 5] = ss;
    __syncthreads();
    if (threadIdx.x == 0) {
        float t = 0.f;
#pragma unroll
        for (int i = 0; i < 8; i++) t += ws[i];
        s_inv = rsqrtf(t / (float)len + 1e-6f);
    }
    __syncthreads();
    const float inv = s_inv;
    __nv_bfloat16* out = dst3 + (size_t)row * 3 * len;
    for (int i = threadIdx.x; i < len; i += 256) {
        __nv_bfloat16 hi, lo;
        bf_split(x[i] * gamma[i] * inv, hi, lo);
        out[3 * i] = hi; out[3 * i + 1] = hi; out[3 * i + 2] = lo;
    }
}

// ---------------- RoPE + pack + split ----------------
__global__ __launch_bounds__(192) void rope_pack_split(
    const float* __restrict__ qp, const float* __restrict__ kvp,
    const float* __restrict__ fused,
    __nv_bfloat16* __restrict__ Q3, __nv_bfloat16* __restrict__ K3,
    __nv_bfloat16* __restrict__ V3)
{
    const int s = blockIdx.x, h = blockIdx.y, d = threadIdx.x;
    const float scale = 0.07216878364870323f; // 1/sqrt(192)
    float qv, kv;
    if (d < DN) {
        qv = qp[(size_t)s * QB_N + h * DFULL + d] * scale;
        kv = kvp[(size_t)s * KVB_N + h * (DN + DV) + d];
        float vv = kvp[(size_t)s * KVB_N + h * (DN + DV) + DN + d];
        __nv_bfloat16 hi, lo;
        bf_split(vv, hi, lo);
        __nv_bfloat16* vp = V3 + ((size_t)h * DV + d) * KP_SEQ + 3 * s;
        vp[0] = hi; vp[1] = lo; vp[2] = hi;   // B-side
    } else {
        int j = d - DN, i = j & 31;
        float inv_freq = powf(10000.f, -(float)(2 * i) / 64.f);
        float sn, cs;
        sincosf((float)s * inv_freq, &sn, &cs);
        size_t qoff = (size_t)s * QB_N + h * DFULL + DN;
        float qpe = qp[qoff + j];
        float qrot = (j < 32) ? -qp[qoff + j + 32] : qp[qoff + j - 32];
        size_t koff = (size_t)s * FUSED_NPAD + (QL + KL);
        float kpe = fused[koff + j];
        float krot = (j < 32) ? -fused[koff + j + 32] : fused[koff + j - 32];
        qv = (qpe * cs + qrot * sn) * scale;
        kv = kpe * cs + krot * sn;
    }
    __nv_bfloat16 qhi, qlo, khi, klo;
    bf_split(qv, qhi, qlo);
    bf_split(kv, khi, klo);
    __nv_bfloat16* qo = Q3 + ((size_t)h * SEQ + s) * KP_D + 3 * d;
    qo[0] = qhi; qo[1] = qhi; qo[2] = qlo;    // A-side
    __nv_bfloat16* ko = K3 + ((size_t)h * SEQ + s) * KP_D + 3 * d;
    ko[0] = khi; ko[1] = klo; ko[2] = khi;    // B-side
}

// ---------------- causal softmax + split (A-side); tail stays zero ----------------
__global__ __launch_bounds__(256) void softmax_split(
    const float* __restrict__ Sc, __nv_bfloat16* __restrict__ P3)
{
    const int q = blockIdx.x, h = blockIdx.y, tid = threadIdx.x;
    const float* row = Sc + ((size_t)h * SEQ + q) * SEQ;
    __nv_bfloat16* out = P3 + ((size_t)h * SEQ + q) * KP_SEQ;
    const int n = q + 1;
    __shared__ float red[8]; __shared__ float bc;

    float mx = -INFINITY;
    for (int i = tid; i < n; i += 256) mx = fmaxf(mx, row[i]);
#pragma unroll
    for (int o = 16; o; o >>= 1) mx = fmaxf(mx, __shfl_xor_sync(0xffffffffu, mx, o));
    if ((tid & 31) == 0) red[tid >> 5] = mx;
    __syncthreads();
    if (tid == 0) {
        float m = red[0];
#pragma unroll
        for (int i = 1; i < 8; i++) m = fmaxf(m, red[i]);
        bc = m;
    }
    __syncthreads();
    const float M = bc;
    float sm = 0.f;
    for (int i = tid; i < n; i += 256) sm += __expf(row[i] - M);
#pragma unroll
    for (int o = 16; o; o >>= 1) sm += __shfl_xor_sync(0xffffffffu, sm, o);
    if ((tid & 31) == 0) red[tid >> 5] = sm;
    __syncthreads();
    if (tid == 0) {
        float t = 0.f;
#pragma unroll
        for (int i = 0; i < 8; i++) t += red[i];
        bc = 1.f / t;
    }
    __syncthreads();
    const float inv = bc;
    for (int i = tid; i < n; i += 256) {
        __nv_bfloat16 hi, lo;
        bf_split(__expf(row[i] - M) * inv, hi, lo);
        out[3 * i] = hi; out[3 * i + 1] = hi; out[3 * i + 2] = lo;
    }
}

// ---------------- launcher ----------------
extern "C" void kernel_launch(void* const* d_in, const int* in_sizes, int n_in,
                              void* d_out, int out_size)
{
    const float* hidden     = (const float*)d_in[0];
    const float* w_kv_a     = (const float*)d_in[1];
    const float* q_a_gamma  = (const float*)d_in[2];
    const float* w_qb       = (const float*)d_in[3];
    const float* kv_a_gamma = (const float*)d_in[4];
    const float* w_kvb      = (const float*)d_in[5];
    const float* w_o        = (const float*)d_in[6];
    float* out = (float*)d_out;

    static float *fused = nullptr, *qp, *kvp, *Sc, *attn;
    static __nv_bfloat16 *H3, *QN3, *KVN3, *ATTN3, *WKVA3, *WQB3, *WKVB3, *WO3, *Q3, *K3, *V3, *P3;
    if (!fused) {
        cudaGetSymbolAddress((void**)&fused, g_fused);
        cudaGetSymbolAddress((void**)&qp,    g_qp);
        cudaGetSymbolAddress((void**)&kvp,   g_kvp);
        cudaGetSymbolAddress((void**)&Sc,    g_Sc);
        cudaGetSymbolAddress((void**)&attn,  g_attn);
        cudaGetSymbolAddress((void**)&H3,    g_H3);
        cudaGetSymbolAddress((void**)&QN3,   g_QN3);
        cudaGetSymbolAddress((void**)&KVN3,  g_KVN3);
        cudaGetSymbolAddress((void**)&ATTN3, g_ATTN3);
        cudaGetSymbolAddress((void**)&WKVA3, g_WKVA3);
        cudaGetSymbolAddress((void**)&WQB3,  g_WQB3);
        cudaGetSymbolAddress((void**)&WKVB3, g_WKVB3);
        cudaGetSymbolAddress((void**)&WO3,   g_WO3);
        cudaGetSymbolAddress((void**)&Q3,    g_Q3);
        cudaGetSymbolAddress((void**)&K3,    g_K3);
        cudaGetSymbolAddress((void**)&V3,    g_V3);
        cudaGetSymbolAddress((void**)&P3,    g_P3);
        cudaFuncSetAttribute(gemm_bf16, cudaFuncAttributeMaxDynamicSharedMemorySize, GSMEM);
    }

    // operand preparation
    split_act<<<(SEQ * HDIM + 255) / 256, 256>>>(hidden, H3, SEQ * HDIM);
    transpose_split_w<<<dim3(HDIM / 32, FUSED_REAL / 32), 1024>>>(w_kv_a, WKVA3, HDIM, FUSED_REAL);
    transpose_split_w<<<dim3(QL / 32, QB_N / 32), 1024>>>(w_qb, WQB3, QL, QB_N);
    transpose_split_w<<<dim3(KL / 32, KVB_N / 32), 1024>>>(w_kvb, WKVB3, KL, KVB_N);
    transpose_split_w<<<dim3(HDIM / 32, HDIM / 32), 1024>>>(w_o, WO3, HDIM, HDIM);

    // 1) fused = hidden @ w_kv_a
    gemm_bf16<<<dim3(FUSED_NPAD / 128, SEQ / 128), 256, GSMEM>>>(
        H3, 0, WKVA3, 0, fused, 0, KP_H, KP_H, FUSED_NPAD, KP_H, 0);

    // 2) rmsnorm + split
    rmsnorm_split<<<SEQ, 256>>>(fused, q_a_gamma, QN3, FUSED_NPAD, QL);
    rmsnorm_split<<<SEQ, 256>>>(fused + QL, kv_a_gamma, KVN3, FUSED_NPAD, KL);

    // 3) projections
    gemm_bf16<<<dim3(QB_N / 128, SEQ / 128), 256, GSMEM>>>(
        QN3, 0, WQB3, 0, qp, 0, KP_QL, KP_QL, QB_N, KP_QL, 0);
    gemm_bf16<<<dim3(KVB_N / 128, SEQ / 128), 256, GSMEM>>>(
        KVN3, 0, WKVB3, 0, kvp, 0, KP_KL, KP_KL, KVB_N, KP_KL, 0);

    // 4) rope + pack + split
    rope_pack_split<<<dim3(SEQ, NH), 192>>>(qp, kvp, fused, Q3, K3, V3);

    // 5) scores = Q @ K^T (causal block-skip), per head
    gemm_bf16<<<dim3(SEQ / 128, SEQ / 128, NH), 256, GSMEM>>>(
        Q3, (long long)SEQ * KP_D, K3, (long long)SEQ * KP_D,
        Sc, (long long)SEQ * SEQ, KP_D, KP_D, SEQ, KP_D, 1);

    // 6) softmax + split
    softmax_split<<<dim3(SEQ, NH), 256>>>(Sc, P3);

    // 7) attn = P @ V (causal k-limit), per head
    gemm_bf16<<<dim3(1, SEQ / 128, NH), 256, GSMEM>>>(
        P3, (long long)SEQ * KP_SEQ, V3, (long long)DV * KP_SEQ,
        attn, (long long)DV, KP_SEQ, KP_SEQ, NH * DV, KP_SEQ, 2);

    // 8) out = attn @ w_o
    split_act<<<(SEQ * HDIM + 255) / 256, 256>>>(attn, ATTN3, SEQ * HDIM);
    gemm_bf16<<<dim3(HDIM / 128, SEQ / 128), 256, GSMEM>>>(
        ATTN3, 0, WO3, 0, out, 0, KP_H, KP_H, HDIM, KP_H, 0);
}